// round 8
// baseline (speedup 1.0000x reference)
#include <cuda_runtime.h>
#include <cuda_bf16.h>
#include <cstdint>

#define NN 100000
#define NE 1000000
#define HD 64
#define NG 1000
#define NH 4
#define NO 128

// ---------------- scratch (device globals; no allocation) ----------------
static __device__ float g_h[NN * HD];
static __device__ float g_res[NN * HD];
static __device__ float g_agg[NN * HD];
static __device__ float g_z[NN * HD];
static __device__ float g_red[2 * HD];
static __device__ float g_bns[2 * HD];
static __device__ float g_bnt[2 * HD];
static __device__ float g_sc[NN * NH];
static __device__ float g_pool[NG * HD];
static __device__ int g_deg[NN];
static __device__ int g_incl[NN];
static __device__ int g_off[NN + 1];
static __device__ int g_cur[NN];
static __device__ int g_bsum[128];
static __device__ int g_bpre[128];
static __device__ int g_esrc[NE];
static __device__ int g_goff[NG + 1];

// ---------------- f32x2 packed FMA helpers (scalar GEMM) ----------------
__device__ __forceinline__ void ffma2(unsigned long long& d,
                                      unsigned long long a,
                                      unsigned long long b) {
    asm("fma.rn.f32x2 %0, %1, %2, %0;" : "+l"(d) : "l"(a), "l"(b));
}
__device__ __forceinline__ unsigned long long bcast2(float x) {
    unsigned long long r;
    asm("mov.b64 %0, {%1, %1};" : "=l"(r) : "f"(x));
    return r;
}

// ================= bf16 3-split tensor-core GEMM (mma.sync) =================
// Y[M,64] = X[M,64] @ W[64,64] + bias, optional relu.
// 128 rows per block, 256 threads (8 warps, 16-row stripe each).
// bf16 split: x = xh + xl, w = wh + wl; D = xh*wh + xh*wl + xl*wh (fp32 acc).

#define AST 68  // smem row stride in bf16 elems (136B; 8B-aligned, bank-clean)

__device__ __forceinline__ void mma16816(float* c, const uint32_t* a,
                                         uint32_t b0, uint32_t b1) {
    asm volatile(
        "mma.sync.aligned.m16n8k16.row.col.f32.bf16.bf16.f32 "
        "{%0,%1,%2,%3}, {%4,%5,%6,%7}, {%8,%9}, {%0,%1,%2,%3};"
        : "+f"(c[0]), "+f"(c[1]), "+f"(c[2]), "+f"(c[3])
        : "r"(a[0]), "r"(a[1]), "r"(a[2]), "r"(a[3]), "r"(b0), "r"(b1));
}

__device__ __forceinline__ uint32_t pack_hi(float f0, float f1) {
    __nv_bfloat16 h0 = __float2bfloat16(f0);
    __nv_bfloat16 h1 = __float2bfloat16(f1);
    return (uint32_t)__bfloat16_as_ushort(h0) |
           ((uint32_t)__bfloat16_as_ushort(h1) << 16);
}
__device__ __forceinline__ uint32_t pack_lo(float f0, float f1) {
    __nv_bfloat16 h0 = __float2bfloat16(f0);
    __nv_bfloat16 h1 = __float2bfloat16(f1);
    __nv_bfloat16 l0 = __float2bfloat16(f0 - __bfloat162float(h0));
    __nv_bfloat16 l1 = __float2bfloat16(f1 - __bfloat162float(h1));
    return (uint32_t)__bfloat16_as_ushort(l0) |
           ((uint32_t)__bfloat16_as_ushort(l1) << 16);
}

__global__ void __launch_bounds__(256)
bgemm(const float* __restrict__ X, const float* __restrict__ W,
      const float* __restrict__ bias, float* __restrict__ Y, int relu) {
    extern __shared__ __nv_bfloat16 sm[];
    __nv_bfloat16* Ah = sm;                 // [128][AST]
    __nv_bfloat16* Al = sm + 128 * AST;     // [128][AST]
    __nv_bfloat16* Bh = sm + 256 * AST;     // [64][AST]
    __nv_bfloat16* Bl = sm + 320 * AST;     // [64][AST]

    int tid = threadIdx.x;
    int wid = tid >> 5;
    int lane = tid & 31;
    int row0 = blockIdx.x << 7;

    // ---- convert A: thread handles (row = tid>>1, k half = (tid&1)*32) ----
    {
        int m = tid >> 1;
        int kh = (tid & 1) * 32;
        int row = row0 + m;
        const float2* xr = (const float2*)(X + (size_t)row * 64 + kh);
#pragma unroll
        for (int j = 0; j < 16; j++) {
            float2 v = (row < NN) ? xr[j] : make_float2(0.f, 0.f);
            uint32_t hi = pack_hi(v.x, v.y);
            uint32_t lo = pack_lo(v.x, v.y);
            *(uint32_t*)&Ah[m * AST + kh + j * 2] = hi;
            *(uint32_t*)&Al[m * AST + kh + j * 2] = lo;
        }
    }
    // ---- convert B: Bs[n][k] = W[k][n] (transpose) ----
    {
#pragma unroll
        for (int i = 0; i < 16; i++) {
            int idx = tid + i * 256;  // 4096 elements
            int k = idx >> 6;
            int n = idx & 63;
            float f = W[idx];
            __nv_bfloat16 h = __float2bfloat16(f);
            __nv_bfloat16 l = __float2bfloat16(f - __bfloat162float(h));
            Bh[n * AST + k] = h;
            Bl[n * AST + k] = l;
        }
    }
    __syncthreads();

    // ---- MMA mainloop: warp stripe m0..m0+15, full N=64 ----
    int m0 = wid * 16;
    int g = lane >> 2;   // 0..7
    int t = lane & 3;    // 0..3
    float acc[8][4];
#pragma unroll
    for (int j = 0; j < 8; j++)
#pragma unroll
        for (int r = 0; r < 4; r++) acc[j][r] = 0.f;

#pragma unroll
    for (int s = 0; s < 4; s++) {
        int k0 = s * 16;
        uint32_t ah[4], al[4];
        ah[0] = *(const uint32_t*)&Ah[(m0 + g) * AST + k0 + t * 2];
        ah[1] = *(const uint32_t*)&Ah[(m0 + g + 8) * AST + k0 + t * 2];
        ah[2] = *(const uint32_t*)&Ah[(m0 + g) * AST + k0 + 8 + t * 2];
        ah[3] = *(const uint32_t*)&Ah[(m0 + g + 8) * AST + k0 + 8 + t * 2];
        al[0] = *(const uint32_t*)&Al[(m0 + g) * AST + k0 + t * 2];
        al[1] = *(const uint32_t*)&Al[(m0 + g + 8) * AST + k0 + t * 2];
        al[2] = *(const uint32_t*)&Al[(m0 + g) * AST + k0 + 8 + t * 2];
        al[3] = *(const uint32_t*)&Al[(m0 + g + 8) * AST + k0 + 8 + t * 2];
#pragma unroll
        for (int j = 0; j < 8; j++) {
            int n0 = j * 8;
            uint32_t bh0 = *(const uint32_t*)&Bh[(n0 + g) * AST + k0 + t * 2];
            uint32_t bh1 =
                *(const uint32_t*)&Bh[(n0 + g) * AST + k0 + 8 + t * 2];
            uint32_t bl0 = *(const uint32_t*)&Bl[(n0 + g) * AST + k0 + t * 2];
            uint32_t bl1 =
                *(const uint32_t*)&Bl[(n0 + g) * AST + k0 + 8 + t * 2];
            mma16816(acc[j], ah, bh0, bh1);
            mma16816(acc[j], ah, bl0, bl1);
            mma16816(acc[j], al, bh0, bh1);
        }
    }

    // ---- epilogue: bias + relu + store ----
    int r0 = row0 + m0 + g;
    int r1 = r0 + 8;
#pragma unroll
    for (int j = 0; j < 8; j++) {
        int c0 = j * 8 + t * 2;
        float b0 = bias[c0], b1 = bias[c0 + 1];
        float o0 = acc[j][0] + b0, o1 = acc[j][1] + b1;
        float o2 = acc[j][2] + b0, o3 = acc[j][3] + b1;
        if (relu) {
            o0 = fmaxf(o0, 0.f); o1 = fmaxf(o1, 0.f);
            o2 = fmaxf(o2, 0.f); o3 = fmaxf(o3, 0.f);
        }
        if (r0 < NN) *(float2*)(Y + (size_t)r0 * 64 + c0) = make_float2(o0, o1);
        if (r1 < NN) *(float2*)(Y + (size_t)r1 * 64 + c0) = make_float2(o2, o3);
    }
}

#define BG_SMEM (384 * AST * 2)  // 52224 bytes

// ---------------- BatchNorm ----------------
__global__ void k_bn_stats(const float* __restrict__ Z) {
    int f = threadIdx.x & 63;
    int rl = threadIdx.x >> 6;
    float s = 0.f, q = 0.f;
    for (int r = blockIdx.x * 4 + rl; r < NN; r += gridDim.x * 4) {
        float v = Z[(size_t)r * HD + f];
        s += v;
        q += v * v;
    }
    __shared__ float sh[512];
    sh[threadIdx.x] = s;
    sh[256 + threadIdx.x] = q;
    __syncthreads();
    if (rl == 0) {
        s = sh[f] + sh[64 + f] + sh[128 + f] + sh[192 + f];
        q = sh[256 + f] + sh[320 + f] + sh[384 + f] + sh[448 + f];
        atomicAdd(&g_red[f], s);
        atomicAdd(&g_red[64 + f], q);
    }
}

__global__ void k_bn_finalize(const float* __restrict__ gamma,
                              const float* __restrict__ beta, int slot) {
    int f = threadIdx.x;  // 64 threads
    float inv_n = 1.f / (float)NN;
    float mu = g_red[f] * inv_n;
    float var = fmaxf(g_red[64 + f] * inv_n - mu * mu, 0.f);
    float rs = rsqrtf(var + 1e-5f);
    float sc = rs * gamma[f];
    g_bns[slot * 64 + f] = sc;
    g_bnt[slot * 64 + f] = beta[f] - mu * sc;
    g_red[f] = 0.f;
    g_red[64 + f] = 0.f;
}

// h = relu(z*s1+t1) + res; res = h   (slot 1)
__global__ void k_resid_fused() {
    int t = blockIdx.x * blockDim.x + threadIdx.x;
    if (t >= NN * 16) return;
    int c4 = t & 15;
    float4 s = ((const float4*)(g_bns + 64))[c4];
    float4 b = ((const float4*)(g_bnt + 64))[c4];
    float4 v = ((const float4*)g_z)[t];
    float4 r = ((const float4*)g_res)[t];
    float4 a;
    a.x = fmaxf(v.x * s.x + b.x, 0.f) + r.x;
    a.y = fmaxf(v.y * s.y + b.y, 0.f) + r.y;
    a.z = fmaxf(v.z * s.z + b.z, 0.f) + r.z;
    a.w = fmaxf(v.w * s.w + b.w, 0.f) + r.w;
    ((float4*)g_h)[t] = a;
    ((float4*)g_res)[t] = a;
}

// ---------------- CSR build ----------------
__global__ void k_deg_zero() {
    int i = blockIdx.x * blockDim.x + threadIdx.x;
    if (i < NN) g_deg[i] = 0;
}

__global__ void k_csr_count(const int* __restrict__ dst) {
    int e = blockIdx.x * blockDim.x + threadIdx.x;
    if (e < NE) atomicAdd(&g_deg[dst[e]], 1);
}

__global__ void k_scan_chunk() {
    __shared__ int ssum[256];
    int blk = blockIdx.x;
    int base = blk * 1024;
    int tid = threadIdx.x;
    int v[4];
    int s = 0;
#pragma unroll
    for (int j = 0; j < 4; j++) {
        int idx = base + tid * 4 + j;
        int d = (idx < NN) ? g_deg[idx] : 0;
        v[j] = d;
        s += d;
    }
    ssum[tid] = s;
    __syncthreads();
    for (int o = 1; o < 256; o <<= 1) {
        int x = (tid >= o) ? ssum[tid - o] : 0;
        __syncthreads();
        ssum[tid] += x;
        __syncthreads();
    }
    int run = ssum[tid] - s;
#pragma unroll
    for (int j = 0; j < 4; j++) {
        run += v[j];
        int idx = base + tid * 4 + j;
        if (idx < NN) g_incl[idx] = run;
    }
    if (tid == 255) g_bsum[blk] = ssum[255];
}

__global__ void k_scan_tops(int nchunks) {
    __shared__ int sh[128];
    int tid = threadIdx.x;
    int v = (tid < nchunks) ? g_bsum[tid] : 0;
    sh[tid] = v;
    __syncthreads();
    for (int o = 1; o < 128; o <<= 1) {
        int x = (tid >= o) ? sh[tid - o] : 0;
        __syncthreads();
        sh[tid] += x;
        __syncthreads();
    }
    g_bpre[tid] = sh[tid] - v;
}

__global__ void k_scan_final() {
    int i = blockIdx.x * blockDim.x + threadIdx.x;
    if (i == 0) g_off[0] = 0;
    if (i < NN) {
        int off_ip1 = g_incl[i] + g_bpre[i >> 10];
        g_off[i + 1] = off_ip1;
        int off_i = (i == 0) ? 0 : (g_incl[i - 1] + g_bpre[(i - 1) >> 10]);
        g_cur[i] = off_i;
    }
}

__global__ void k_csr_fill(const int* __restrict__ src,
                           const int* __restrict__ dst) {
    int e = blockIdx.x * blockDim.x + threadIdx.x;
    if (e >= NE) return;
    int d = dst[e];
    int pos = atomicAdd(&g_cur[d], 1);
    g_esrc[pos] = src[e];
}

__global__ void k_goff(const int* __restrict__ batch) {
    int i = blockIdx.x * blockDim.x + threadIdx.x;
    if (i >= NN) return;
    int b = batch[i];
    if (i == 0) {
        for (int g = 0; g <= b; g++) g_goff[g] = 0;
    } else {
        int p = batch[i - 1];
        for (int g = p + 1; g <= b; g++) g_goff[g] = i;
    }
    if (i == NN - 1) {
        for (int g = b + 1; g <= NG; g++) g_goff[g] = NN;
    }
}

// ---- gather: agg[n] = f(X[n]) + sum f(X[src]); f = affine+relu if aff ----
__device__ __forceinline__ float4 xf4(float4 v, float4 s, float4 b, int aff) {
    if (!aff) return v;
    float4 o;
    o.x = fmaxf(v.x * s.x + b.x, 0.f);
    o.y = fmaxf(v.y * s.y + b.y, 0.f);
    o.z = fmaxf(v.z * s.z + b.z, 0.f);
    o.w = fmaxf(v.w * s.w + b.w, 0.f);
    return o;
}

__global__ void k_gather(const float* __restrict__ X, int aff) {
    int t = blockIdx.x * blockDim.x + threadIdx.x;
    int n = t >> 4;
    if (n >= NN) return;
    int l = t & 15;
    float4 s = make_float4(1.f, 1.f, 1.f, 1.f);
    float4 b = make_float4(0.f, 0.f, 0.f, 0.f);
    if (aff) {  // slot 0
        s = ((const float4*)g_bns)[l];
        b = ((const float4*)g_bnt)[l];
    }
    int beg = g_off[n], end = g_off[n + 1];
    float4 acc = xf4(((const float4*)X)[(size_t)n * 16 + l], s, b, aff);
    int e = beg;
    for (; e + 4 <= end; e += 4) {
        int s0 = __ldg(&g_esrc[e + 0]);
        int s1 = __ldg(&g_esrc[e + 1]);
        int s2 = __ldg(&g_esrc[e + 2]);
        int s3 = __ldg(&g_esrc[e + 3]);
        float4 v0 = ((const float4*)X)[(size_t)s0 * 16 + l];
        float4 v1 = ((const float4*)X)[(size_t)s1 * 16 + l];
        float4 v2 = ((const float4*)X)[(size_t)s2 * 16 + l];
        float4 v3 = ((const float4*)X)[(size_t)s3 * 16 + l];
        v0 = xf4(v0, s, b, aff);
        v1 = xf4(v1, s, b, aff);
        v2 = xf4(v2, s, b, aff);
        v3 = xf4(v3, s, b, aff);
        acc.x += v0.x + v1.x + v2.x + v3.x;
        acc.y += v0.y + v1.y + v2.y + v3.y;
        acc.z += v0.z + v1.z + v2.z + v3.z;
        acc.w += v0.w + v1.w + v2.w + v3.w;
    }
    for (; e < end; e++) {
        int si = __ldg(&g_esrc[e]);
        float4 v = xf4(((const float4*)X)[(size_t)si * 16 + l], s, b, aff);
        acc.x += v.x; acc.y += v.y; acc.z += v.z; acc.w += v.w;
    }
    ((float4*)g_agg)[(size_t)n * 16 + l] = acc;
}

// ---------------- scalar GEMM (proj / attention / output) ----------
__global__ void __launch_bounds__(128, 4)
gemm128(const float* __restrict__ X, const float* __restrict__ W,
        const float* __restrict__ bias, float* __restrict__ Y,
        float* __restrict__ Y2, int M, int relu,
        const float* __restrict__ inscale, const float* __restrict__ inshift,
        const float* __restrict__ seed, float* __restrict__ scout) {
    __shared__ float Ws[64 * 64];
    __shared__ float Xs[128 * 64];
    int tid = threadIdx.x;
    int row0 = blockIdx.x << 7;

    {
        const float4* W4 = (const float4*)W;
        float4* Ws4 = (float4*)Ws;
#pragma unroll
        for (int i = 0; i < 8; i++) Ws4[tid + 128 * i] = W4[tid + 128 * i];
    }
    {
        int c4 = tid & 15;
        int r0 = tid >> 4;
        float4 scl = make_float4(1.f, 1.f, 1.f, 1.f);
        float4 sht = make_float4(0.f, 0.f, 0.f, 0.f);
        if (inscale) {
            scl = ((const float4*)inscale)[c4];
            sht = ((const float4*)inshift)[c4];
        }
#pragma unroll
        for (int i = 0; i < 16; i++) {
            int m = r0 + 8 * i;
            int row = row0 + m;
            float4 v = make_float4(0.f, 0.f, 0.f, 0.f);
            if (row < M) v = ((const float4*)X)[(size_t)row * 16 + c4];
            v.x = v.x * scl.x + sht.x;
            v.y = v.y * scl.y + sht.y;
            v.z = v.z * scl.z + sht.z;
            v.w = v.w * scl.w + sht.w;
            int cs = (c4 ^ (m >> 3)) & 15;
            *(float4*)&Xs[m * 64 + cs * 4] = v;
        }
    }
    __syncthreads();

    int tx = tid & 7;
    int ty = tid >> 3;

    unsigned long long acc[8][4];
#pragma unroll
    for (int r = 0; r < 8; r++)
#pragma unroll
        for (int j = 0; j < 4; j++) acc[r][j] = 0ull;

#pragma unroll
    for (int k4 = 0; k4 < 16; k4++) {
        float4 xv[8];
        int cs = (k4 ^ ty) & 15;
#pragma unroll
        for (int r = 0; r < 8; r++) {
            int m = ty * 8 + r;
            xv[r] = *(const float4*)&Xs[m * 64 + cs * 4];
        }
#pragma unroll
        for (int kk = 0; kk < 4; kk++) {
            int k = k4 * 4 + kk;
            ulonglong2 w0 = *(const ulonglong2*)&Ws[k * 64 + tx * 8];
            ulonglong2 w1 = *(const ulonglong2*)&Ws[k * 64 + tx * 8 + 4];
#pragma unroll
            for (int r = 0; r < 8; r++) {
                float xs = (kk == 0) ? xv[r].x
                         : (kk == 1) ? xv[r].y
                         : (kk == 2) ? xv[r].z : xv[r].w;
                unsigned long long xx = bcast2(xs);
                ffma2(acc[r][0], xx, w0.x);
                ffma2(acc[r][1], xx, w0.y);
                ffma2(acc[r][2], xx, w1.x);
                ffma2(acc[r][3], xx, w1.y);
            }
        }
    }

    float bv[8];
#pragma unroll
    for (int j = 0; j < 8; j++) bv[j] = 0.f;
    if (bias) {
        float4 b0 = ((const float4*)bias)[tx * 2];
        float4 b1 = ((const float4*)bias)[tx * 2 + 1];
        bv[0] = b0.x; bv[1] = b0.y; bv[2] = b0.z; bv[3] = b0.w;
        bv[4] = b1.x; bv[5] = b1.y; bv[6] = b1.z; bv[7] = b1.w;
    }
    float sv[8];
    if (seed) {
#pragma unroll
        for (int j = 0; j < 8; j++) sv[j] = seed[tx * 8 + j];
    }

#pragma unroll
    for (int r = 0; r < 8; r++) {
        int row = row0 + ty * 8 + r;
        bool ok = row < M;
        float o[8];
#pragma unroll
        for (int j = 0; j < 4; j++) {
            float2 p = *(float2*)&acc[r][j];
            o[2 * j] = p.x + bv[2 * j];
            o[2 * j + 1] = p.y + bv[2 * j + 1];
        }
        if (relu) {
#pragma unroll
            for (int j = 0; j < 8; j++) o[j] = fmaxf(o[j], 0.f);
        }
        if (seed) {
            float p = 0.f;
#pragma unroll
            for (int j = 0; j < 8; j++) p += o[j] * sv[j];
            p += __shfl_xor_sync(0xffffffffu, p, 1);
            if (ok && (tx & 1) == 0) scout[row * NH + (tx >> 1)] = p * 0.25f;
        }
        if (ok && Y) {
            float4 a = make_float4(o[0], o[1], o[2], o[3]);
            float4 b = make_float4(o[4], o[5], o[6], o[7]);
            ((float4*)Y)[(size_t)row * 16 + tx * 2] = a;
            ((float4*)Y)[(size_t)row * 16 + tx * 2 + 1] = b;
            if (Y2) {
                ((float4*)Y2)[(size_t)row * 16 + tx * 2] = a;
                ((float4*)Y2)[(size_t)row * 16 + tx * 2 + 1] = b;
            }
        }
    }
}

// ---------------- attention readout: one block per graph ----------------
__global__ void k_attn() {
    int g = blockIdx.x;
    int tid = threadIdx.x;  // 128
    int beg = g_goff[g], end = g_goff[g + 1];
    __shared__ float shm[4 * 4];
    __shared__ float shs[4 * 4];
    __shared__ float mx[4], sm[4];
    __shared__ float pacc[64];

    float m0 = -1e30f, m1 = -1e30f, m2 = -1e30f, m3 = -1e30f;
    for (int n = beg + tid; n < end; n += 128) {
        float4 v = ((const float4*)g_sc)[n];
        m0 = fmaxf(m0, v.x); m1 = fmaxf(m1, v.y);
        m2 = fmaxf(m2, v.z); m3 = fmaxf(m3, v.w);
    }
#pragma unroll
    for (int o = 16; o; o >>= 1) {
        m0 = fmaxf(m0, __shfl_xor_sync(0xffffffffu, m0, o));
        m1 = fmaxf(m1, __shfl_xor_sync(0xffffffffu, m1, o));
        m2 = fmaxf(m2, __shfl_xor_sync(0xffffffffu, m2, o));
        m3 = fmaxf(m3, __shfl_xor_sync(0xffffffffu, m3, o));
    }
    if ((tid & 31) == 0) {
        int w = tid >> 5;
        shm[w * 4 + 0] = m0; shm[w * 4 + 1] = m1;
        shm[w * 4 + 2] = m2; shm[w * 4 + 3] = m3;
    }
    __syncthreads();
    if (tid < 4) {
        mx[tid] = fmaxf(fmaxf(shm[tid], shm[4 + tid]),
                        fmaxf(shm[8 + tid], shm[12 + tid]));
    }
    __syncthreads();

    float s0 = 0.f, s1 = 0.f, s2 = 0.f, s3 = 0.f;
    float q0 = mx[0], q1 = mx[1], q2 = mx[2], q3 = mx[3];
    for (int n = beg + tid; n < end; n += 128) {
        float4 v = ((const float4*)g_sc)[n];
        v.x = expf(v.x - q0); v.y = expf(v.y - q1);
        v.z = expf(v.z - q2); v.w = expf(v.w - q3);
        ((float4*)g_sc)[n] = v;
        s0 += v.x; s1 += v.y; s2 += v.z; s3 += v.w;
    }
#pragma unroll
    for (int o = 16; o; o >>= 1) {
        s0 += __shfl_xor_sync(0xffffffffu, s0, o);
        s1 += __shfl_xor_sync(0xffffffffu, s1, o);
        s2 += __shfl_xor_sync(0xffffffffu, s2, o);
        s3 += __shfl_xor_sync(0xffffffffu, s3, o);
    }
    if ((tid & 31) == 0) {
        int w = tid >> 5;
        shs[w * 4 + 0] = s0; shs[w * 4 + 1] = s1;
        shs[w * 4 + 2] = s2; shs[w * 4 + 3] = s3;
    }
    __syncthreads();
    if (tid < 4) {
        float t = shs[tid] + shs[4 + tid] + shs[8 + tid] + shs[12 + tid];
        sm[tid] = (t > 0.f) ? (1.f / t) : 0.f;
    }
    if (tid < 64) pacc[tid] = 0.f;
    __syncthreads();

    int c = tid & 63;
    int half = tid >> 6;
    int hh = c >> 4;
    float acc = 0.f;
    for (int n = beg + half; n < end; n += 2) {
        float w = g_sc[n * NH + hh];
        acc += w * g_agg[(size_t)n * HD + c];
    }
    if (half == 1) atomicAdd(&pacc[c], acc);
    __syncthreads();
    if (half == 0) g_pool[g * HD + c] = (acc + pacc[c]) * sm[hh];
}

__global__ void k_logits(const float* __restrict__ embed,
                         const float* __restrict__ W,
                         const float* __restrict__ b, float* __restrict__ out) {
    int g = blockIdx.x;
    int t = threadIdx.x;  // 128
    __shared__ float e[64];
    if (t < 64) e[t] = embed[g * 64 + t];
    __syncthreads();
    float s = b[t];
#pragma unroll
    for (int k = 0; k < 64; k++) s += e[k] * W[k * NO + t];
    out[g * NO + t] = s;
}

// ---------------- launch ----------------
extern "C" void kernel_launch(void* const* d_in, const int* in_sizes, int n_in,
                              void* d_out, int out_size) {
    const float* x = (const float*)d_in[0];
    const int* ei = (const int*)d_in[1];
    const int* batch = (const int*)d_in[2];
    const float* fng = (const float*)d_in[3];
    const float* fnb = (const float*)d_in[4];
    const float* projW = (const float*)d_in[5];
    const float* projb = (const float*)d_in[6];
    const float* mlpW = (const float*)d_in[7];
    const float* mlpb = (const float*)d_in[8];
    const float* ng = (const float*)d_in[9];
    const float* nb = (const float*)d_in[10];
    const float* seed = (const float*)d_in[11];
    const float* Wk = (const float*)d_in[12];
    const float* Wv = (const float*)d_in[13];
    const float* Wo = (const float*)d_in[14];
    const float* predW = (const float*)d_in[15];
    const float* predb = (const float*)d_in[16];
    float* out = (float*)d_out;

    float *h, *res, *agg, *z, *pool, *bns, *bnt, *sc;
    cudaGetSymbolAddress((void**)&h, g_h);
    cudaGetSymbolAddress((void**)&res, g_res);
    cudaGetSymbolAddress((void**)&agg, g_agg);
    cudaGetSymbolAddress((void**)&z, g_z);
    cudaGetSymbolAddress((void**)&pool, g_pool);
    cudaGetSymbolAddress((void**)&bns, g_bns);
    cudaGetSymbolAddress((void**)&bnt, g_bnt);
    cudaGetSymbolAddress((void**)&sc, g_sc);

    cudaFuncSetAttribute(bgemm, cudaFuncAttributeMaxDynamicSharedMemorySize,
                         BG_SMEM);

    const int* src = ei;
    const int* dst = ei + NE;

    const int GB = (NN + 127) / 128;       // 782
    const int EW = (NN * 16 + 255) / 256;
    const int EB = (NE + 255) / 256;
    const int NB = (NN + 255) / 256;
    const int GTB = (NN * 16 + 255) / 256;
    const int NCHUNK = (NN + 1023) / 1024;

    k_bn_stats<<<256, 256>>>(x);
    k_deg_zero<<<NB, 256>>>();
    k_bn_finalize<<<1, 64>>>(fng, fnb, 0);
    gemm128<<<GB, 128>>>(x, projW, projb, h, res, NN, 1, bns, bnt, nullptr,
                         nullptr);
    k_csr_count<<<EB, 256>>>(dst);
    k_scan_chunk<<<NCHUNK, 256>>>();
    k_scan_tops<<<1, 128>>>(NCHUNK);
    k_scan_final<<<NB, 256>>>();
    k_csr_fill<<<EB, 256>>>(src, dst);
    k_goff<<<NB, 256>>>(batch);

    for (int m = 0; m < 4; m++) {
        const float* Wm = mlpW + m * 3 * 4096;
        const float* bm = mlpb + m * 3 * 64;
        // c = 0: gather(h, plain) -> agg
        k_gather<<<GTB, 256>>>(h, 0);
        bgemm<<<GB, 256, BG_SMEM>>>(agg, Wm, bm, z, 1);
        bgemm<<<GB, 256, BG_SMEM>>>(z, Wm + 4096, bm + 64, agg, 1);
        bgemm<<<GB, 256, BG_SMEM>>>(agg, Wm + 8192, bm + 128, z, 0);
        k_bn_stats<<<256, 256>>>(z);
        k_bn_finalize<<<1, 64>>>(ng + m * 64, nb + m * 64, 0);
        // c = 1: gather(bnrelu(z), slot 0) -> agg
        k_gather<<<GTB, 256>>>(z, 1);
        bgemm<<<GB, 256, BG_SMEM>>>(agg, Wm, bm, z, 1);
        bgemm<<<GB, 256, BG_SMEM>>>(z, Wm + 4096, bm + 64, agg, 1);
        bgemm<<<GB, 256, BG_SMEM>>>(agg, Wm + 8192, bm + 128, z, 0);
        k_bn_stats<<<256, 256>>>(z);
        k_bn_finalize<<<1, 64>>>(ng + m * 64, nb + m * 64, 1);
        // h = relu(bn(z)) + res; res = h
        k_resid_fused<<<EW, 256>>>();
    }

    // attention: scores fused into Wk GEMM; V -> agg
    gemm128<<<GB, 128>>>(h, Wk, nullptr, nullptr, nullptr, NN, 0, nullptr,
                         nullptr, seed, sc);
    gemm128<<<GB, 128>>>(h, Wv, nullptr, agg, nullptr, NN, 0, nullptr, nullptr,
                         nullptr, nullptr);
    k_attn<<<NG, 128>>>();

    gemm128<<<(NG + 127) / 128, 128>>>(pool, Wo, nullptr, out, nullptr, NG, 0,
                                       nullptr, nullptr, nullptr, nullptr);
    k_logits<<<NG, 128>>>(out, predW, predb, out + NG * HD);
}

// round 9
// speedup vs baseline: 1.1898x; 1.1898x over previous
#include <cuda_runtime.h>
#include <cstdint>

#define NN 100000
#define NE 1000000
#define HD 64
#define NG 1000
#define NH 4
#define NO 128

// ---------------- scratch (device globals; no allocation) ----------------
static __device__ float g_h[NN * HD];
static __device__ float g_res[NN * HD];
static __device__ float g_agg[NN * HD];
static __device__ float g_z[NN * HD];
static __device__ float g_red[2 * HD];     // zero at entry; finalize re-zeroes
static __device__ float g_bns[2 * HD];
static __device__ float g_bnt[2 * HD];
static __device__ float g_sc[NN * NH];
static __device__ float g_pool[NG * HD];
static __device__ int g_deg[NN];
static __device__ int g_incl[NN];
static __device__ int g_off[NN + 1];
static __device__ int g_cur[NN];
static __device__ int g_bsum[128];
static __device__ int g_bpre[128];
static __device__ int g_esrc[NE];
static __device__ int g_goff[NG + 1];

// ---------------- f32x2 packed FMA helpers ----------------
__device__ __forceinline__ void ffma2(unsigned long long& d,
                                      unsigned long long a,
                                      unsigned long long b) {
    asm("fma.rn.f32x2 %0, %1, %2, %0;" : "+l"(d) : "l"(a), "l"(b));
}
__device__ __forceinline__ unsigned long long bcast2(float x) {
    unsigned long long r;
    asm("mov.b64 %0, {%1, %1};" : "=l"(r) : "f"(x));
    return r;
}

// ---------------- BatchNorm ----------------
__global__ void k_bn_stats(const float* __restrict__ Z) {
    int f = threadIdx.x & 63;
    int rl = threadIdx.x >> 6;
    float s = 0.f, q = 0.f;
    for (int r = blockIdx.x * 4 + rl; r < NN; r += gridDim.x * 4) {
        float v = Z[(size_t)r * HD + f];
        s += v;
        q += v * v;
    }
    __shared__ float sh[512];
    sh[threadIdx.x] = s;
    sh[256 + threadIdx.x] = q;
    __syncthreads();
    if (rl == 0) {
        s = sh[f] + sh[64 + f] + sh[128 + f] + sh[192 + f];
        q = sh[256 + f] + sh[320 + f] + sh[384 + f] + sh[448 + f];
        atomicAdd(&g_red[f], s);
        atomicAdd(&g_red[64 + f], q);
    }
}

__global__ void k_bn_finalize(const float* __restrict__ gamma,
                              const float* __restrict__ beta, int slot) {
    int f = threadIdx.x;  // 64 threads
    float inv_n = 1.f / (float)NN;
    float mu = g_red[f] * inv_n;
    float var = fmaxf(g_red[64 + f] * inv_n - mu * mu, 0.f);
    float rs = rsqrtf(var + 1e-5f);
    float sc = rs * gamma[f];
    g_bns[slot * 64 + f] = sc;
    g_bnt[slot * 64 + f] = beta[f] - mu * sc;
    g_red[f] = 0.f;
    g_red[64 + f] = 0.f;
}

// h = relu(z*s1+t1) + res; res = h   (slot 1)
__global__ void k_resid_fused() {
    int t = blockIdx.x * blockDim.x + threadIdx.x;
    if (t >= NN * 16) return;
    int c4 = t & 15;
    float4 s = ((const float4*)(g_bns + 64))[c4];
    float4 b = ((const float4*)(g_bnt + 64))[c4];
    float4 v = ((const float4*)g_z)[t];
    float4 r = ((const float4*)g_res)[t];
    float4 a;
    a.x = fmaxf(v.x * s.x + b.x, 0.f) + r.x;
    a.y = fmaxf(v.y * s.y + b.y, 0.f) + r.y;
    a.z = fmaxf(v.z * s.z + b.z, 0.f) + r.z;
    a.w = fmaxf(v.w * s.w + b.w, 0.f) + r.w;
    ((float4*)g_h)[t] = a;
    ((float4*)g_res)[t] = a;
}

// ---------------- CSR build ----------------
__global__ void k_deg_zero() {
    int i = blockIdx.x * blockDim.x + threadIdx.x;
    if (i < NN) g_deg[i] = 0;
}

__global__ void k_csr_count(const int* __restrict__ dst) {
    int e = blockIdx.x * blockDim.x + threadIdx.x;
    if (e < NE) atomicAdd(&g_deg[dst[e]], 1);
}

__global__ void k_scan_chunk() {
    __shared__ int ssum[256];
    int blk = blockIdx.x;
    int base = blk * 1024;
    int tid = threadIdx.x;
    int v[4];
    int s = 0;
#pragma unroll
    for (int j = 0; j < 4; j++) {
        int idx = base + tid * 4 + j;
        int d = (idx < NN) ? g_deg[idx] : 0;
        v[j] = d;
        s += d;
    }
    ssum[tid] = s;
    __syncthreads();
    for (int o = 1; o < 256; o <<= 1) {
        int x = (tid >= o) ? ssum[tid - o] : 0;
        __syncthreads();
        ssum[tid] += x;
        __syncthreads();
    }
    int run = ssum[tid] - s;
#pragma unroll
    for (int j = 0; j < 4; j++) {
        run += v[j];
        int idx = base + tid * 4 + j;
        if (idx < NN) g_incl[idx] = run;
    }
    if (tid == 255) g_bsum[blk] = ssum[255];
}

__global__ void k_scan_tops(int nchunks) {
    __shared__ int sh[128];
    int tid = threadIdx.x;
    int v = (tid < nchunks) ? g_bsum[tid] : 0;
    sh[tid] = v;
    __syncthreads();
    for (int o = 1; o < 128; o <<= 1) {
        int x = (tid >= o) ? sh[tid - o] : 0;
        __syncthreads();
        sh[tid] += x;
        __syncthreads();
    }
    g_bpre[tid] = sh[tid] - v;
}

__global__ void k_scan_final() {
    int i = blockIdx.x * blockDim.x + threadIdx.x;
    if (i == 0) g_off[0] = 0;
    if (i < NN) {
        int off_ip1 = g_incl[i] + g_bpre[i >> 10];
        g_off[i + 1] = off_ip1;
        int off_i = (i == 0) ? 0 : (g_incl[i - 1] + g_bpre[(i - 1) >> 10]);
        g_cur[i] = off_i;
    }
}

__global__ void k_csr_fill(const int* __restrict__ src,
                           const int* __restrict__ dst) {
    int e = blockIdx.x * blockDim.x + threadIdx.x;
    if (e >= NE) return;
    int d = dst[e];
    int pos = atomicAdd(&g_cur[d], 1);
    g_esrc[pos] = src[e];
}

__global__ void k_goff(const int* __restrict__ batch) {
    int i = blockIdx.x * blockDim.x + threadIdx.x;
    if (i >= NN) return;
    int b = batch[i];
    if (i == 0) {
        for (int g = 0; g <= b; g++) g_goff[g] = 0;
    } else {
        int p = batch[i - 1];
        for (int g = p + 1; g <= b; g++) g_goff[g] = i;
    }
    if (i == NN - 1) {
        for (int g = b + 1; g <= NG; g++) g_goff[g] = NN;
    }
}

// ---- gather: agg[n] = f(X[n]) + sum f(X[src]); f = affine+relu if aff ----
__device__ __forceinline__ float4 xf4(float4 v, float4 s, float4 b, int aff) {
    if (!aff) return v;
    float4 o;
    o.x = fmaxf(v.x * s.x + b.x, 0.f);
    o.y = fmaxf(v.y * s.y + b.y, 0.f);
    o.z = fmaxf(v.z * s.z + b.z, 0.f);
    o.w = fmaxf(v.w * s.w + b.w, 0.f);
    return o;
}

__global__ void k_gather(const float* __restrict__ X, int aff) {
    int t = blockIdx.x * blockDim.x + threadIdx.x;
    int n = t >> 4;
    if (n >= NN) return;
    int l = t & 15;
    float4 s = make_float4(1.f, 1.f, 1.f, 1.f);
    float4 b = make_float4(0.f, 0.f, 0.f, 0.f);
    if (aff) {  // slot 0
        s = ((const float4*)g_bns)[l];
        b = ((const float4*)g_bnt)[l];
    }
    int beg = g_off[n], end = g_off[n + 1];
    float4 acc = xf4(((const float4*)X)[(size_t)n * 16 + l], s, b, aff);
    int e = beg;
    for (; e + 4 <= end; e += 4) {
        int s0 = __ldg(&g_esrc[e + 0]);
        int s1 = __ldg(&g_esrc[e + 1]);
        int s2 = __ldg(&g_esrc[e + 2]);
        int s3 = __ldg(&g_esrc[e + 3]);
        float4 v0 = ((const float4*)X)[(size_t)s0 * 16 + l];
        float4 v1 = ((const float4*)X)[(size_t)s1 * 16 + l];
        float4 v2 = ((const float4*)X)[(size_t)s2 * 16 + l];
        float4 v3 = ((const float4*)X)[(size_t)s3 * 16 + l];
        v0 = xf4(v0, s, b, aff);
        v1 = xf4(v1, s, b, aff);
        v2 = xf4(v2, s, b, aff);
        v3 = xf4(v3, s, b, aff);
        acc.x += v0.x + v1.x + v2.x + v3.x;
        acc.y += v0.y + v1.y + v2.y + v3.y;
        acc.z += v0.z + v1.z + v2.z + v3.z;
        acc.w += v0.w + v1.w + v2.w + v3.w;
    }
    for (; e < end; e++) {
        int si = __ldg(&g_esrc[e]);
        float4 v = xf4(((const float4*)X)[(size_t)si * 16 + l], s, b, aff);
        acc.x += v.x; acc.y += v.y; acc.z += v.z; acc.w += v.w;
    }
    ((float4*)g_agg)[(size_t)n * 16 + l] = acc;
}

// ================= fused 3-GEMM MLP: Z = L3(relu(L2(relu(L1(X))))) =======
// No gather inside (X = g_agg, pre-materialized) -> no cross-block races.
// 256 threads, 128-row tile, 4x8 micro-tile, f32x2 FMA.
// Intermediates stay in the smem X tile; BN stats fused into final phase.
__global__ void __launch_bounds__(256, 3)
k_mlp3(const float* __restrict__ X, const float* __restrict__ W3,
       const float* __restrict__ b3, float* __restrict__ Z) {
    __shared__ float Ws[64 * 64];   // 16 KB, reloaded per phase
    __shared__ float Xs[128 * 64];  // 32 KB, rewritten per phase
    int tid = threadIdx.x;
    int row0 = blockIdx.x << 7;
    int tx = tid & 7;   // cols tx*8 .. tx*8+7
    int ty = tid >> 3;  // rows ty*4 .. ty*4+3 (ty 0..31)

    // load X tile from global (swizzle slot = (c4 ^ (m>>2)) & 15)
    {
        int c4 = tid & 15;
        int r0 = tid >> 4;  // 0..15
#pragma unroll
        for (int i = 0; i < 8; i++) {
            int m = r0 + 16 * i;
            int row = row0 + m;
            float4 v = make_float4(0.f, 0.f, 0.f, 0.f);
            if (row < NN) v = ((const float4*)X)[(size_t)row * 16 + c4];
            int cs = (c4 ^ (m >> 2)) & 15;
            *(float4*)&Xs[m * 64 + cs * 4] = v;
        }
    }
    // load phase-0 weights
    {
        const float4* W4 = (const float4*)W3;
        float4* Ws4 = (float4*)Ws;
#pragma unroll
        for (int i = 0; i < 4; i++) Ws4[tid + 256 * i] = W4[tid + 256 * i];
    }
    __syncthreads();

    unsigned long long acc[4][4];

#pragma unroll 1
    for (int ph = 0; ph < 3; ph++) {
#pragma unroll
        for (int r = 0; r < 4; r++)
#pragma unroll
            for (int j = 0; j < 4; j++) acc[r][j] = 0ull;

#pragma unroll
        for (int k4 = 0; k4 < 16; k4++) {
            int cs = (k4 ^ ty) & 15;
            float4 xv[4];
#pragma unroll
            for (int r = 0; r < 4; r++)
                xv[r] = *(const float4*)&Xs[(ty * 4 + r) * 64 + cs * 4];
#pragma unroll
            for (int kk = 0; kk < 4; kk++) {
                int k = k4 * 4 + kk;
                ulonglong2 w0 = *(const ulonglong2*)&Ws[k * 64 + tx * 8];
                ulonglong2 w1 = *(const ulonglong2*)&Ws[k * 64 + tx * 8 + 4];
#pragma unroll
                for (int r = 0; r < 4; r++) {
                    float xs = (kk == 0) ? xv[r].x
                             : (kk == 1) ? xv[r].y
                             : (kk == 2) ? xv[r].z : xv[r].w;
                    unsigned long long xx = bcast2(xs);
                    ffma2(acc[r][0], xx, w0.x);
                    ffma2(acc[r][1], xx, w0.y);
                    ffma2(acc[r][2], xx, w1.x);
                    ffma2(acc[r][3], xx, w1.y);
                }
            }
        }

        // bias (+relu for phases 0,1), in place in acc
        const float* bias = b3 + ph * 64;
        bool last = (ph == 2);
#pragma unroll
        for (int j = 0; j < 4; j++) {
            float b0 = bias[tx * 8 + 2 * j];
            float b1 = bias[tx * 8 + 2 * j + 1];
#pragma unroll
            for (int r = 0; r < 4; r++) {
                float2 p = *(float2*)&acc[r][j];
                p.x += b0;
                p.y += b1;
                if (!last) {
                    p.x = fmaxf(p.x, 0.f);
                    p.y = fmaxf(p.y, 0.f);
                }
                *(float2*)&acc[r][j] = p;
            }
        }

        __syncthreads();  // all Xs/Ws reads of this phase done
        if (!last) {
            // write phase output back into Xs (same swizzle family, key ty)
#pragma unroll
            for (int r = 0; r < 4; r++) {
                int m = ty * 4 + r;
                int sa = ((tx * 2) ^ ty) & 15;
                int sb = ((tx * 2 + 1) ^ ty) & 15;
                float2 p0 = *(float2*)&acc[r][0];
                float2 p1 = *(float2*)&acc[r][1];
                float2 p2 = *(float2*)&acc[r][2];
                float2 p3 = *(float2*)&acc[r][3];
                *(float4*)&Xs[m * 64 + sa * 4] =
                    make_float4(p0.x, p0.y, p1.x, p1.y);
                *(float4*)&Xs[m * 64 + sb * 4] =
                    make_float4(p2.x, p2.y, p3.x, p3.y);
            }
            // load next-phase weights
            const float4* W4 = (const float4*)(W3 + (ph + 1) * 4096);
            float4* Ws4 = (float4*)Ws;
#pragma unroll
            for (int i = 0; i < 4; i++) Ws4[tid + 256 * i] = W4[tid + 256 * i];
            __syncthreads();
        }
    }

    // ---- final: write Z + fused BN stats ----
    float s[8], q[8];
#pragma unroll
    for (int j = 0; j < 8; j++) { s[j] = 0.f; q[j] = 0.f; }
#pragma unroll
    for (int r = 0; r < 4; r++) {
        int row = row0 + ty * 4 + r;
        if (row >= NN) continue;
        float2 p0 = *(float2*)&acc[r][0];
        float2 p1 = *(float2*)&acc[r][1];
        float2 p2 = *(float2*)&acc[r][2];
        float2 p3 = *(float2*)&acc[r][3];
        float o[8] = {p0.x, p0.y, p1.x, p1.y, p2.x, p2.y, p3.x, p3.y};
#pragma unroll
        for (int j = 0; j < 8; j++) {
            s[j] += o[j];
            q[j] += o[j] * o[j];
        }
        ((float4*)Z)[(size_t)row * 16 + tx * 2] =
            make_float4(o[0], o[1], o[2], o[3]);
        ((float4*)Z)[(size_t)row * 16 + tx * 2 + 1] =
            make_float4(o[4], o[5], o[6], o[7]);
    }
    {
        float* red = Xs;  // scratch [2][64][33] = 16.9 KB
#pragma unroll
        for (int j = 0; j < 8; j++) {
            int c = tx * 8 + j;
            red[c * 33 + ty] = s[j];
            red[64 * 33 + c * 33 + ty] = q[j];
        }
        __syncthreads();
        if (tid < 128) {
            int c = tid & 63;
            int which = tid >> 6;
            float t = 0.f;
#pragma unroll
            for (int i = 0; i < 32; i++) t += red[which * 64 * 33 + c * 33 + i];
            atomicAdd(&g_red[which * 64 + c], t);
        }
    }
}

// ---------------- scalar GEMM (proj / attention / output) ----------
__global__ void __launch_bounds__(128, 4)
gemm128(const float* __restrict__ X, const float* __restrict__ W,
        const float* __restrict__ bias, float* __restrict__ Y,
        float* __restrict__ Y2, int M, int relu,
        const float* __restrict__ inscale, const float* __restrict__ inshift,
        const float* __restrict__ seed, float* __restrict__ scout) {
    __shared__ float Ws[64 * 64];
    __shared__ float Xs[128 * 64];
    int tid = threadIdx.x;
    int row0 = blockIdx.x << 7;

    {
        const float4* W4 = (const float4*)W;
        float4* Ws4 = (float4*)Ws;
#pragma unroll
        for (int i = 0; i < 8; i++) Ws4[tid + 128 * i] = W4[tid + 128 * i];
    }
    {
        int c4 = tid & 15;
        int r0 = tid >> 4;
        float4 scl = make_float4(1.f, 1.f, 1.f, 1.f);
        float4 sht = make_float4(0.f, 0.f, 0.f, 0.f);
        if (inscale) {
            scl = ((const float4*)inscale)[c4];
            sht = ((const float4*)inshift)[c4];
        }
#pragma unroll
        for (int i = 0; i < 16; i++) {
            int m = r0 + 8 * i;
            int row = row0 + m;
            float4 v = make_float4(0.f, 0.f, 0.f, 0.f);
            if (row < M) v = ((const float4*)X)[(size_t)row * 16 + c4];
            v.x = v.x * scl.x + sht.x;
            v.y = v.y * scl.y + sht.y;
            v.z = v.z * scl.z + sht.z;
            v.w = v.w * scl.w + sht.w;
            int cs = (c4 ^ (m >> 3)) & 15;
            *(float4*)&Xs[m * 64 + cs * 4] = v;
        }
    }
    __syncthreads();

    int tx = tid & 7;
    int ty = tid >> 3;

    unsigned long long acc[8][4];
#pragma unroll
    for (int r = 0; r < 8; r++)
#pragma unroll
        for (int j = 0; j < 4; j++) acc[r][j] = 0ull;

#pragma unroll
    for (int k4 = 0; k4 < 16; k4++) {
        float4 xv[8];
        int cs = (k4 ^ ty) & 15;
#pragma unroll
        for (int r = 0; r < 8; r++) {
            int m = ty * 8 + r;
            xv[r] = *(const float4*)&Xs[m * 64 + cs * 4];
        }
#pragma unroll
        for (int kk = 0; kk < 4; kk++) {
            int k = k4 * 4 + kk;
            ulonglong2 w0 = *(const ulonglong2*)&Ws[k * 64 + tx * 8];
            ulonglong2 w1 = *(const ulonglong2*)&Ws[k * 64 + tx * 8 + 4];
#pragma unroll
            for (int r = 0; r < 8; r++) {
                float xs = (kk == 0) ? xv[r].x
                         : (kk == 1) ? xv[r].y
                         : (kk == 2) ? xv[r].z : xv[r].w;
                unsigned long long xx = bcast2(xs);
                ffma2(acc[r][0], xx, w0.x);
                ffma2(acc[r][1], xx, w0.y);
                ffma2(acc[r][2], xx, w1.x);
                ffma2(acc[r][3], xx, w1.y);
            }
        }
    }

    float bv[8];
#pragma unroll
    for (int j = 0; j < 8; j++) bv[j] = 0.f;
    if (bias) {
        float4 b0 = ((const float4*)bias)[tx * 2];
        float4 b1 = ((const float4*)bias)[tx * 2 + 1];
        bv[0] = b0.x; bv[1] = b0.y; bv[2] = b0.z; bv[3] = b0.w;
        bv[4] = b1.x; bv[5] = b1.y; bv[6] = b1.z; bv[7] = b1.w;
    }
    float sv[8];
    if (seed) {
#pragma unroll
        for (int j = 0; j < 8; j++) sv[j] = seed[tx * 8 + j];
    }

#pragma unroll
    for (int r = 0; r < 8; r++) {
        int row = row0 + ty * 8 + r;
        bool ok = row < M;
        float o[8];
#pragma unroll
        for (int j = 0; j < 4; j++) {
            float2 p = *(float2*)&acc[r][j];
            o[2 * j] = p.x + bv[2 * j];
            o[2 * j + 1] = p.y + bv[2 * j + 1];
        }
        if (relu) {
#pragma unroll
            for (int j = 0; j < 8; j++) o[j] = fmaxf(o[j], 0.f);
        }
        if (seed) {
            float p = 0.f;
#pragma unroll
            for (int j = 0; j < 8; j++) p += o[j] * sv[j];
            p += __shfl_xor_sync(0xffffffffu, p, 1);
            if (ok && (tx & 1) == 0) scout[row * NH + (tx >> 1)] = p * 0.25f;
        }
        if (ok && Y) {
            float4 a = make_float4(o[0], o[1], o[2], o[3]);
            float4 b = make_float4(o[4], o[5], o[6], o[7]);
            ((float4*)Y)[(size_t)row * 16 + tx * 2] = a;
            ((float4*)Y)[(size_t)row * 16 + tx * 2 + 1] = b;
            if (Y2) {
                ((float4*)Y2)[(size_t)row * 16 + tx * 2] = a;
                ((float4*)Y2)[(size_t)row * 16 + tx * 2 + 1] = b;
            }
        }
    }
}

// ---------------- attention readout: one block per graph ----------------
__global__ void k_attn() {
    int g = blockIdx.x;
    int tid = threadIdx.x;  // 128
    int beg = g_goff[g], end = g_goff[g + 1];
    __shared__ float shm[4 * 4];
    __shared__ float shs[4 * 4];
    __shared__ float mx[4], sm[4];
    __shared__ float pacc[64];

    float m0 = -1e30f, m1 = -1e30f, m2 = -1e30f, m3 = -1e30f;
    for (int n = beg + tid; n < end; n += 128) {
        float4 v = ((const float4*)g_sc)[n];
        m0 = fmaxf(m0, v.x); m1 = fmaxf(m1, v.y);
        m2 = fmaxf(m2, v.z); m3 = fmaxf(m3, v.w);
    }
#pragma unroll
    for (int o = 16; o; o >>= 1) {
        m0 = fmaxf(m0, __shfl_xor_sync(0xffffffffu, m0, o));
        m1 = fmaxf(m1, __shfl_xor_sync(0xffffffffu, m1, o));
        m2 = fmaxf(m2, __shfl_xor_sync(0xffffffffu, m2, o));
        m3 = fmaxf(m3, __shfl_xor_sync(0xffffffffu, m3, o));
    }
    if ((tid & 31) == 0) {
        int w = tid >> 5;
        shm[w * 4 + 0] = m0; shm[w * 4 + 1] = m1;
        shm[w * 4 + 2] = m2; shm[w * 4 + 3] = m3;
    }
    __syncthreads();
    if (tid < 4) {
        mx[tid] = fmaxf(fmaxf(shm[tid], shm[4 + tid]),
                        fmaxf(shm[8 + tid], shm[12 + tid]));
    }
    __syncthreads();

    float s0 = 0.f, s1 = 0.f, s2 = 0.f, s3 = 0.f;
    float q0 = mx[0], q1 = mx[1], q2 = mx[2], q3 = mx[3];
    for (int n = beg + tid; n < end; n += 128) {
        float4 v = ((const float4*)g_sc)[n];
        v.x = expf(v.x - q0); v.y = expf(v.y - q1);
        v.z = expf(v.z - q2); v.w = expf(v.w - q3);
        ((float4*)g_sc)[n] = v;
        s0 += v.x; s1 += v.y; s2 += v.z; s3 += v.w;
    }
#pragma unroll
    for (int o = 16; o; o >>= 1) {
        s0 += __shfl_xor_sync(0xffffffffu, s0, o);
        s1 += __shfl_xor_sync(0xffffffffu, s1, o);
        s2 += __shfl_xor_sync(0xffffffffu, s2, o);
        s3 += __shfl_xor_sync(0xffffffffu, s3, o);
    }
    if ((tid & 31) == 0) {
        int w = tid >> 5;
        shs[w * 4 + 0] = s0; shs[w * 4 + 1] = s1;
        shs[w * 4 + 2] = s2; shs[w * 4 + 3] = s3;
    }
    __syncthreads();
    if (tid < 4) {
        float t = shs[tid] + shs[4 + tid] + shs[8 + tid] + shs[12 + tid];
        sm[tid] = (t > 0.f) ? (1.f / t) : 0.f;
    }
    if (tid < 64) pacc[tid] = 0.f;
    __syncthreads();

    int c = tid & 63;
    int half = tid >> 6;
    int hh = c >> 4;
    float acc = 0.f;
    for (int n = beg + half; n < end; n += 2) {
        float w = g_sc[n * NH + hh];
        acc += w * g_agg[(size_t)n * HD + c];
    }
    if (half == 1) atomicAdd(&pacc[c], acc);
    __syncthreads();
    if (half == 0) g_pool[g * HD + c] = (acc + pacc[c]) * sm[hh];
}

__global__ void k_logits(const float* __restrict__ embed,
                         const float* __restrict__ W,
                         const float* __restrict__ b, float* __restrict__ out) {
    int g = blockIdx.x;
    int t = threadIdx.x;  // 128
    __shared__ float e[64];
    if (t < 64) e[t] = embed[g * 64 + t];
    __syncthreads();
    float s = b[t];
#pragma unroll
    for (int k = 0; k < 64; k++) s += e[k] * W[k * NO + t];
    out[g * NO + t] = s;
}

// ---------------- launch ----------------
extern "C" void kernel_launch(void* const* d_in, const int* in_sizes, int n_in,
                              void* d_out, int out_size) {
    const float* x = (const float*)d_in[0];
    const int* ei = (const int*)d_in[1];
    const int* batch = (const int*)d_in[2];
    const float* fng = (const float*)d_in[3];
    const float* fnb = (const float*)d_in[4];
    const float* projW = (const float*)d_in[5];
    const float* projb = (const float*)d_in[6];
    const float* mlpW = (const float*)d_in[7];
    const float* mlpb = (const float*)d_in[8];
    const float* ng = (const float*)d_in[9];
    const float* nb = (const float*)d_in[10];
    const float* seed = (const float*)d_in[11];
    const float* Wk = (const float*)d_in[12];
    const float* Wv = (const float*)d_in[13];
    const float* Wo = (const float*)d_in[14];
    const float* predW = (const float*)d_in[15];
    const float* predb = (const float*)d_in[16];
    float* out = (float*)d_out;

    float *h, *res, *agg, *z, *pool, *bns, *bnt, *sc;
    cudaGetSymbolAddress((void**)&h, g_h);
    cudaGetSymbolAddress((void**)&res, g_res);
    cudaGetSymbolAddress((void**)&agg, g_agg);
    cudaGetSymbolAddress((void**)&z, g_z);
    cudaGetSymbolAddress((void**)&pool, g_pool);
    cudaGetSymbolAddress((void**)&bns, g_bns);
    cudaGetSymbolAddress((void**)&bnt, g_bnt);
    cudaGetSymbolAddress((void**)&sc, g_sc);

    const int* src = ei;
    const int* dst = ei + NE;

    const int GB = (NN + 127) / 128;       // 782
    const int EW = (NN * 16 + 255) / 256;
    const int EB = (NE + 255) / 256;
    const int NB = (NN + 255) / 256;
    const int GTB = (NN * 16 + 255) / 256;
    const int NCHUNK = (NN + 1023) / 1024;

    // proj GEMM kept at launch index 3 for the profiler.
    k_bn_stats<<<256, 256>>>(x);
    k_deg_zero<<<NB, 256>>>();
    k_bn_finalize<<<1, 64>>>(fng, fnb, 0);
    gemm128<<<GB, 128>>>(x, projW, projb, h, res, NN, 1, bns, bnt, nullptr,
                         nullptr);
    k_csr_count<<<EB, 256>>>(dst);
    k_scan_chunk<<<NCHUNK, 256>>>();
    k_scan_tops<<<1, 128>>>(NCHUNK);
    k_scan_final<<<NB, 256>>>();
    k_csr_fill<<<EB, 256>>>(src, dst);
    k_goff<<<NB, 256>>>(batch);

    for (int m = 0; m < 4; m++) {
        const float* Wm = mlpW + m * 3 * 4096;
        const float* bm = mlpb + m * 3 * 64;
        // c = 0: gather(h, plain) -> agg; fused MLP agg -> z (+BN stats)
        k_gather<<<GTB, 256>>>(h, 0);
        k_mlp3<<<GB, 256>>>(agg, Wm, bm, z);
        k_bn_finalize<<<1, 64>>>(ng + m * 64, nb + m * 64, 0);
        // c = 1: gather(bnrelu(z), slot 0) -> agg; fused MLP agg -> z
        k_gather<<<GTB, 256>>>(z, 1);
        k_mlp3<<<GB, 256>>>(agg, Wm, bm, z);
        k_bn_finalize<<<1, 64>>>(ng + m * 64, nb + m * 64, 1);
        // h = relu(bn(z)) + res; res = h
        k_resid_fused<<<EW, 256>>>();
    }

    // attention: scores fused into Wk GEMM; V -> agg
    gemm128<<<GB, 128>>>(h, Wk, nullptr, nullptr, nullptr, NN, 0, nullptr,
                         nullptr, seed, sc);
    gemm128<<<GB, 128>>>(h, Wv, nullptr, agg, nullptr, NN, 0, nullptr, nullptr,
                         nullptr, nullptr);
    k_attn<<<NG, 128>>>();

    gemm128<<<(NG + 127) / 128, 128>>>(pool, Wo, nullptr, out, nullptr, NG, 0,
                                       nullptr, nullptr, nullptr, nullptr);
    k_logits<<<NG, 128>>>(out, predW, predb, out + NG * HD);
}

// round 10
// speedup vs baseline: 1.5156x; 1.2739x over previous
#include <cuda_runtime.h>

#define NN 100000
#define NE 1000000
#define HD 64
#define NG 1000
#define NH 4
#define NO 128

// ---------------- scratch (device globals; no allocation) ----------------
// Working set kept at 3 big buffers (h, agg, z) = 76.8 MB so it stays
// L2-resident (126 MB) -- g_res was removed (res == h invariantly).
static __device__ float g_h[NN * HD];
static __device__ float g_agg[NN * HD];
static __device__ float g_z[NN * HD];
static __device__ float g_red[2 * HD];     // zero at entry; finalize re-zeroes
static __device__ float g_bns[2 * HD];     // BN scale, 2 slots
static __device__ float g_bnt[2 * HD];     // BN shift, 2 slots
static __device__ float g_sc[NN * NH];
static __device__ float g_pool[NG * HD];
// CSR scratch
static __device__ int g_deg[NN];
static __device__ int g_incl[NN];
static __device__ int g_off[NN + 1];
static __device__ int g_cur[NN];
static __device__ int g_bsum[128];
static __device__ int g_bpre[128];
static __device__ int g_esrc[NE];
static __device__ int g_goff[NG + 1];

// ---------------- f32x2 packed FMA helpers ----------------
__device__ __forceinline__ void ffma2(unsigned long long& d,
                                      unsigned long long a,
                                      unsigned long long b) {
    asm("fma.rn.f32x2 %0, %1, %2, %0;" : "+l"(d) : "l"(a), "l"(b));
}
__device__ __forceinline__ unsigned long long bcast2(float x) {
    unsigned long long r;
    asm("mov.b64 %0, {%1, %1};" : "=l"(r) : "f"(x));
    return r;
}

// ---------------- BatchNorm ----------------
__global__ void k_bn_stats(const float* __restrict__ Z) {
    int f = threadIdx.x & 63;
    int rl = threadIdx.x >> 6;  // 0..3
    float s = 0.f, q = 0.f;
    for (int r = blockIdx.x * 4 + rl; r < NN; r += gridDim.x * 4) {
        float v = Z[(size_t)r * HD + f];
        s += v;
        q += v * v;
    }
    __shared__ float sh[512];
    sh[threadIdx.x] = s;
    sh[256 + threadIdx.x] = q;
    __syncthreads();
    if (rl == 0) {
        s = sh[f] + sh[64 + f] + sh[128 + f] + sh[192 + f];
        q = sh[256 + f] + sh[320 + f] + sh[384 + f] + sh[448 + f];
        atomicAdd(&g_red[f], s);
        atomicAdd(&g_red[64 + f], q);
    }
}

// computes BN scale/shift into slot, then zeroes g_red (keeps invariant)
__global__ void k_bn_finalize(const float* __restrict__ gamma,
                              const float* __restrict__ beta, int slot) {
    int f = threadIdx.x;  // 64 threads
    float inv_n = 1.f / (float)NN;
    float mu = g_red[f] * inv_n;
    float var = fmaxf(g_red[64 + f] * inv_n - mu * mu, 0.f);
    float rs = rsqrtf(var + 1e-5f);
    float sc = rs * gamma[f];
    g_bns[slot * 64 + f] = sc;
    g_bnt[slot * 64 + f] = beta[f] - mu * sc;
    g_red[f] = 0.f;
    g_red[64 + f] = 0.f;
}

// h = relu(z*s1+t1) + h   (slot 1; res == h invariant, so no res buffer)
__global__ void k_resid_fused() {
    int t = blockIdx.x * blockDim.x + threadIdx.x;
    if (t >= NN * 16) return;
    int c4 = t & 15;
    float4 s = ((const float4*)(g_bns + 64))[c4];
    float4 b = ((const float4*)(g_bnt + 64))[c4];
    float4 v = ((const float4*)g_z)[t];
    float4 r = ((const float4*)g_h)[t];
    float4 a;
    a.x = fmaxf(v.x * s.x + b.x, 0.f) + r.x;
    a.y = fmaxf(v.y * s.y + b.y, 0.f) + r.y;
    a.z = fmaxf(v.z * s.z + b.z, 0.f) + r.z;
    a.w = fmaxf(v.w * s.w + b.w, 0.f) + r.w;
    ((float4*)g_h)[t] = a;
}

// ---------------- CSR build ----------------
__global__ void k_deg_zero() {
    int i = blockIdx.x * blockDim.x + threadIdx.x;
    if (i < NN) g_deg[i] = 0;
}

__global__ void k_csr_count(const int* __restrict__ dst) {
    int e = blockIdx.x * blockDim.x + threadIdx.x;
    if (e < NE) atomicAdd(&g_deg[dst[e]], 1);
}

__global__ void k_scan_chunk() {
    __shared__ int ssum[256];
    int blk = blockIdx.x;
    int base = blk * 1024;
    int tid = threadIdx.x;
    int v[4];
    int s = 0;
#pragma unroll
    for (int j = 0; j < 4; j++) {
        int idx = base + tid * 4 + j;
        int d = (idx < NN) ? g_deg[idx] : 0;
        v[j] = d;
        s += d;
    }
    ssum[tid] = s;
    __syncthreads();
    for (int o = 1; o < 256; o <<= 1) {
        int x = (tid >= o) ? ssum[tid - o] : 0;
        __syncthreads();
        ssum[tid] += x;
        __syncthreads();
    }
    int run = ssum[tid] - s;
#pragma unroll
    for (int j = 0; j < 4; j++) {
        run += v[j];
        int idx = base + tid * 4 + j;
        if (idx < NN) g_incl[idx] = run;
    }
    if (tid == 255) g_bsum[blk] = ssum[255];
}

__global__ void k_scan_tops(int nchunks) {
    __shared__ int sh[128];
    int tid = threadIdx.x;
    int v = (tid < nchunks) ? g_bsum[tid] : 0;
    sh[tid] = v;
    __syncthreads();
    for (int o = 1; o < 128; o <<= 1) {
        int x = (tid >= o) ? sh[tid - o] : 0;
        __syncthreads();
        sh[tid] += x;
        __syncthreads();
    }
    g_bpre[tid] = sh[tid] - v;
}

__global__ void k_scan_final() {
    int i = blockIdx.x * blockDim.x + threadIdx.x;
    if (i == 0) g_off[0] = 0;
    if (i < NN) {
        int off_ip1 = g_incl[i] + g_bpre[i >> 10];
        g_off[i + 1] = off_ip1;
        int off_i = (i == 0) ? 0 : (g_incl[i - 1] + g_bpre[(i - 1) >> 10]);
        g_cur[i] = off_i;
    }
}

__global__ void k_csr_fill(const int* __restrict__ src,
                           const int* __restrict__ dst) {
    int e = blockIdx.x * blockDim.x + threadIdx.x;
    if (e >= NE) return;
    int d = dst[e];
    int pos = atomicAdd(&g_cur[d], 1);
    g_esrc[pos] = src[e];
}

__global__ void k_goff(const int* __restrict__ batch) {
    int i = blockIdx.x * blockDim.x + threadIdx.x;
    if (i >= NN) return;
    int b = batch[i];
    if (i == 0) {
        for (int g = 0; g <= b; g++) g_goff[g] = 0;
    } else {
        int p = batch[i - 1];
        for (int g = p + 1; g <= b; g++) g_goff[g] = i;
    }
    if (i == NN - 1) {
        for (int g = b + 1; g <= NG; g++) g_goff[g] = NN;
    }
}

// ---- gather: agg[n] = f(X[n]) + sum f(X[src]); f = affine+relu if aff ----
__device__ __forceinline__ float4 xf4(float4 v, float4 s, float4 b, int aff) {
    if (!aff) return v;
    float4 o;
    o.x = fmaxf(v.x * s.x + b.x, 0.f);
    o.y = fmaxf(v.y * s.y + b.y, 0.f);
    o.z = fmaxf(v.z * s.z + b.z, 0.f);
    o.w = fmaxf(v.w * s.w + b.w, 0.f);
    return o;
}

__global__ void k_gather(const float* __restrict__ X, int aff) {
    int t = blockIdx.x * blockDim.x + threadIdx.x;
    int n = t >> 4;
    if (n >= NN) return;
    int l = t & 15;
    float4 s = make_float4(1.f, 1.f, 1.f, 1.f);
    float4 b = make_float4(0.f, 0.f, 0.f, 0.f);
    if (aff) {  // slot 0
        s = ((const float4*)g_bns)[l];
        b = ((const float4*)g_bnt)[l];
    }
    int beg = g_off[n], end = g_off[n + 1];
    float4 acc = xf4(((const float4*)X)[(size_t)n * 16 + l], s, b, aff);
    int e = beg;
    for (; e + 4 <= end; e += 4) {
        int s0 = __ldg(&g_esrc[e + 0]);
        int s1 = __ldg(&g_esrc[e + 1]);
        int s2 = __ldg(&g_esrc[e + 2]);
        int s3 = __ldg(&g_esrc[e + 3]);
        float4 v0 = ((const float4*)X)[(size_t)s0 * 16 + l];
        float4 v1 = ((const float4*)X)[(size_t)s1 * 16 + l];
        float4 v2 = ((const float4*)X)[(size_t)s2 * 16 + l];
        float4 v3 = ((const float4*)X)[(size_t)s3 * 16 + l];
        v0 = xf4(v0, s, b, aff);
        v1 = xf4(v1, s, b, aff);
        v2 = xf4(v2, s, b, aff);
        v3 = xf4(v3, s, b, aff);
        acc.x += v0.x + v1.x + v2.x + v3.x;
        acc.y += v0.y + v1.y + v2.y + v3.y;
        acc.z += v0.z + v1.z + v2.z + v3.z;
        acc.w += v0.w + v1.w + v2.w + v3.w;
    }
    for (; e < end; e++) {
        int si = __ldg(&g_esrc[e]);
        float4 v = xf4(((const float4*)X)[(size_t)si * 16 + l], s, b, aff);
        acc.x += v.x; acc.y += v.y; acc.z += v.z; acc.w += v.w;
    }
    ((float4*)g_agg)[(size_t)n * 16 + l] = acc;
}

// ---------------- GEMM: Y = op(X) @ W + b ----------------
// 128-row tile x 64 cols, 128 threads, 8x8 micro-tile, packed f32x2 FMA.
// Options: input affine (BN fold), relu, fused BN stats,
// fused attention score (seed != null: write scout instead of Y).
__global__ void __launch_bounds__(128, 4)
gemm128(const float* __restrict__ X, const float* __restrict__ W,
        const float* __restrict__ bias, float* __restrict__ Y, int M, int relu,
        const float* __restrict__ inscale, const float* __restrict__ inshift,
        int bnstat, const float* __restrict__ seed, float* __restrict__ scout) {
    __shared__ float Ws[64 * 64];
    __shared__ float Xs[128 * 64];
    int tid = threadIdx.x;
    int row0 = blockIdx.x << 7;

    {
        const float4* W4 = (const float4*)W;
        float4* Ws4 = (float4*)Ws;
#pragma unroll
        for (int i = 0; i < 8; i++) Ws4[tid + 128 * i] = W4[tid + 128 * i];
    }
    {
        int c4 = tid & 15;
        int r0 = tid >> 4;
        float4 scl = make_float4(1.f, 1.f, 1.f, 1.f);
        float4 sht = make_float4(0.f, 0.f, 0.f, 0.f);
        if (inscale) {
            scl = ((const float4*)inscale)[c4];
            sht = ((const float4*)inshift)[c4];
        }
#pragma unroll
        for (int i = 0; i < 16; i++) {
            int m = r0 + 8 * i;
            int row = row0 + m;
            float4 v = make_float4(0.f, 0.f, 0.f, 0.f);
            if (row < M) v = ((const float4*)X)[(size_t)row * 16 + c4];
            v.x = v.x * scl.x + sht.x;
            v.y = v.y * scl.y + sht.y;
            v.z = v.z * scl.z + sht.z;
            v.w = v.w * scl.w + sht.w;
            int cs = (c4 ^ (m >> 3)) & 15;
            *(float4*)&Xs[m * 64 + cs * 4] = v;
        }
    }
    __syncthreads();

    int tx = tid & 7;
    int ty = tid >> 3;

    unsigned long long acc[8][4];
#pragma unroll
    for (int r = 0; r < 8; r++)
#pragma unroll
        for (int j = 0; j < 4; j++) acc[r][j] = 0ull;

#pragma unroll
    for (int k4 = 0; k4 < 16; k4++) {
        float4 xv[8];
        int cs = (k4 ^ ty) & 15;
#pragma unroll
        for (int r = 0; r < 8; r++) {
            int m = ty * 8 + r;
            xv[r] = *(const float4*)&Xs[m * 64 + cs * 4];
        }
#pragma unroll
        for (int kk = 0; kk < 4; kk++) {
            int k = k4 * 4 + kk;
            ulonglong2 w0 = *(const ulonglong2*)&Ws[k * 64 + tx * 8];
            ulonglong2 w1 = *(const ulonglong2*)&Ws[k * 64 + tx * 8 + 4];
#pragma unroll
            for (int r = 0; r < 8; r++) {
                float xs = (kk == 0) ? xv[r].x
                         : (kk == 1) ? xv[r].y
                         : (kk == 2) ? xv[r].z : xv[r].w;
                unsigned long long xx = bcast2(xs);
                ffma2(acc[r][0], xx, w0.x);
                ffma2(acc[r][1], xx, w0.y);
                ffma2(acc[r][2], xx, w1.x);
                ffma2(acc[r][3], xx, w1.y);
            }
        }
    }

    float bv[8];
#pragma unroll
    for (int j = 0; j < 8; j++) bv[j] = 0.f;
    if (bias) {
        float4 b0 = ((const float4*)bias)[tx * 2];
        float4 b1 = ((const float4*)bias)[tx * 2 + 1];
        bv[0] = b0.x; bv[1] = b0.y; bv[2] = b0.z; bv[3] = b0.w;
        bv[4] = b1.x; bv[5] = b1.y; bv[6] = b1.z; bv[7] = b1.w;
    }
    float sv[8];
    if (seed) {
#pragma unroll
        for (int j = 0; j < 8; j++) sv[j] = seed[tx * 8 + j];
    }
    float s[8], q[8];
#pragma unroll
    for (int j = 0; j < 8; j++) { s[j] = 0.f; q[j] = 0.f; }

#pragma unroll
    for (int r = 0; r < 8; r++) {
        int row = row0 + ty * 8 + r;
        bool ok = row < M;
        float o[8];
#pragma unroll
        for (int j = 0; j < 4; j++) {
            float2 p = *(float2*)&acc[r][j];
            o[2 * j] = p.x + bv[2 * j];
            o[2 * j + 1] = p.y + bv[2 * j + 1];
        }
        if (relu) {
#pragma unroll
            for (int j = 0; j < 8; j++) o[j] = fmaxf(o[j], 0.f);
        }
        if (bnstat && ok) {
#pragma unroll
            for (int j = 0; j < 8; j++) {
                s[j] += o[j];
                q[j] += o[j] * o[j];
            }
        }
        if (seed) {
            float p = 0.f;
#pragma unroll
            for (int j = 0; j < 8; j++) p += o[j] * sv[j];
            p += __shfl_xor_sync(0xffffffffu, p, 1);
            if (ok && (tx & 1) == 0) scout[row * NH + (tx >> 1)] = p * 0.25f;
        }
        if (ok && Y) {
            float4 a = make_float4(o[0], o[1], o[2], o[3]);
            float4 b = make_float4(o[4], o[5], o[6], o[7]);
            ((float4*)Y)[(size_t)row * 16 + tx * 2] = a;
            ((float4*)Y)[(size_t)row * 16 + tx * 2 + 1] = b;
        }
    }

    if (bnstat) {
        __syncthreads();
        float* red = Xs;
#pragma unroll
        for (int j = 0; j < 8; j++) {
            int c = tx * 8 + j;
            red[c * 17 + ty] = s[j];
            red[64 * 17 + c * 17 + ty] = q[j];
        }
        __syncthreads();
        {
            int c = tid & 63;
            int which = tid >> 6;
            float t = 0.f;
#pragma unroll
            for (int i = 0; i < 16; i++) t += red[which * 64 * 17 + c * 17 + i];
            atomicAdd(&g_red[which * 64 + c], t);
        }
    }
}

// ---------------- attention readout: one block per graph ----------------
__global__ void k_attn() {
    int g = blockIdx.x;
    int tid = threadIdx.x;  // 128
    int beg = g_goff[g], end = g_goff[g + 1];
    __shared__ float shm[4 * 4];
    __shared__ float shs[4 * 4];
    __shared__ float mx[4], sm[4];
    __shared__ float pacc[64];

    float m0 = -1e30f, m1 = -1e30f, m2 = -1e30f, m3 = -1e30f;
    for (int n = beg + tid; n < end; n += 128) {
        float4 v = ((const float4*)g_sc)[n];
        m0 = fmaxf(m0, v.x); m1 = fmaxf(m1, v.y);
        m2 = fmaxf(m2, v.z); m3 = fmaxf(m3, v.w);
    }
#pragma unroll
    for (int o = 16; o; o >>= 1) {
        m0 = fmaxf(m0, __shfl_xor_sync(0xffffffffu, m0, o));
        m1 = fmaxf(m1, __shfl_xor_sync(0xffffffffu, m1, o));
        m2 = fmaxf(m2, __shfl_xor_sync(0xffffffffu, m2, o));
        m3 = fmaxf(m3, __shfl_xor_sync(0xffffffffu, m3, o));
    }
    if ((tid & 31) == 0) {
        int w = tid >> 5;
        shm[w * 4 + 0] = m0; shm[w * 4 + 1] = m1;
        shm[w * 4 + 2] = m2; shm[w * 4 + 3] = m3;
    }
    __syncthreads();
    if (tid < 4) {
        mx[tid] = fmaxf(fmaxf(shm[tid], shm[4 + tid]),
                        fmaxf(shm[8 + tid], shm[12 + tid]));
    }
    __syncthreads();

    float s0 = 0.f, s1 = 0.f, s2 = 0.f, s3 = 0.f;
    float q0 = mx[0], q1 = mx[1], q2 = mx[2], q3 = mx[3];
    for (int n = beg + tid; n < end; n += 128) {
        float4 v = ((const float4*)g_sc)[n];
        v.x = expf(v.x - q0); v.y = expf(v.y - q1);
        v.z = expf(v.z - q2); v.w = expf(v.w - q3);
        ((float4*)g_sc)[n] = v;
        s0 += v.x; s1 += v.y; s2 += v.z; s3 += v.w;
    }
#pragma unroll
    for (int o = 16; o; o >>= 1) {
        s0 += __shfl_xor_sync(0xffffffffu, s0, o);
        s1 += __shfl_xor_sync(0xffffffffu, s1, o);
        s2 += __shfl_xor_sync(0xffffffffu, s2, o);
        s3 += __shfl_xor_sync(0xffffffffu, s3, o);
    }
    if ((tid & 31) == 0) {
        int w = tid >> 5;
        shs[w * 4 + 0] = s0; shs[w * 4 + 1] = s1;
        shs[w * 4 + 2] = s2; shs[w * 4 + 3] = s3;
    }
    __syncthreads();
    if (tid < 4) {
        float t = shs[tid] + shs[4 + tid] + shs[8 + tid] + shs[12 + tid];
        sm[tid] = (t > 0.f) ? (1.f / t) : 0.f;
    }
    if (tid < 64) pacc[tid] = 0.f;
    __syncthreads();

    int c = tid & 63;
    int half = tid >> 6;
    int hh = c >> 4;
    float acc = 0.f;
    for (int n = beg + half; n < end; n += 2) {
        float w = g_sc[n * NH + hh];
        acc += w * g_agg[(size_t)n * HD + c];
    }
    if (half == 1) atomicAdd(&pacc[c], acc);
    __syncthreads();
    if (half == 0) g_pool[g * HD + c] = (acc + pacc[c]) * sm[hh];
}

__global__ void k_logits(const float* __restrict__ embed,
                         const float* __restrict__ W,
                         const float* __restrict__ b, float* __restrict__ out) {
    int g = blockIdx.x;
    int t = threadIdx.x;  // 128
    __shared__ float e[64];
    if (t < 64) e[t] = embed[g * 64 + t];
    __syncthreads();
    float s = b[t];
#pragma unroll
    for (int k = 0; k < 64; k++) s += e[k] * W[k * NO + t];
    out[g * NO + t] = s;
}

// ---------------- launch ----------------
extern "C" void kernel_launch(void* const* d_in, const int* in_sizes, int n_in,
                              void* d_out, int out_size) {
    const float* x = (const float*)d_in[0];
    const int* ei = (const int*)d_in[1];
    const int* batch = (const int*)d_in[2];
    const float* fng = (const float*)d_in[3];
    const float* fnb = (const float*)d_in[4];
    const float* projW = (const float*)d_in[5];
    const float* projb = (const float*)d_in[6];
    const float* mlpW = (const float*)d_in[7];
    const float* mlpb = (const float*)d_in[8];
    const float* ng = (const float*)d_in[9];
    const float* nb = (const float*)d_in[10];
    const float* seed = (const float*)d_in[11];
    const float* Wk = (const float*)d_in[12];
    const float* Wv = (const float*)d_in[13];
    const float* Wo = (const float*)d_in[14];
    const float* predW = (const float*)d_in[15];
    const float* predb = (const float*)d_in[16];
    float* out = (float*)d_out;

    float *h, *agg, *z, *pool, *bns, *bnt, *sc;
    cudaGetSymbolAddress((void**)&h, g_h);
    cudaGetSymbolAddress((void**)&agg, g_agg);
    cudaGetSymbolAddress((void**)&z, g_z);
    cudaGetSymbolAddress((void**)&pool, g_pool);
    cudaGetSymbolAddress((void**)&bns, g_bns);
    cudaGetSymbolAddress((void**)&bnt, g_bnt);
    cudaGetSymbolAddress((void**)&sc, g_sc);

    const int* src = ei;
    const int* dst = ei + NE;

    const int GB = (NN + 127) / 128;       // 782
    const int EW = (NN * 16 + 255) / 256;
    const int EB = (NE + 255) / 256;
    const int NB = (NN + 255) / 256;
    const int GTB = (NN * 16 + 255) / 256;
    const int NCHUNK = (NN + 1023) / 1024;

    // proj GEMM kept at launch index 3 for the profiler.
    k_bn_stats<<<256, 256>>>(x);
    k_deg_zero<<<NB, 256>>>();
    k_bn_finalize<<<1, 64>>>(fng, fnb, 0);
    gemm128<<<GB, 128>>>(x, projW, projb, h, NN, 1, bns, bnt, 0, nullptr,
                         nullptr);
    k_csr_count<<<EB, 256>>>(dst);
    k_scan_chunk<<<NCHUNK, 256>>>();
    k_scan_tops<<<1, 128>>>(NCHUNK);
    k_scan_final<<<NB, 256>>>();
    k_csr_fill<<<EB, 256>>>(src, dst);
    k_goff<<<NB, 256>>>(batch);

    for (int m = 0; m < 4; m++) {
        const float* Wm = mlpW + m * 3 * 4096;
        const float* bm = mlpb + m * 3 * 64;
        // c = 0: gather(h, plain) -> agg ; MLP agg->z->agg->z (+BN stats)
        k_gather<<<GTB, 256>>>(h, 0);
        gemm128<<<GB, 128>>>(agg, Wm, bm, z, NN, 1, nullptr, nullptr, 0,
                             nullptr, nullptr);
        gemm128<<<GB, 128>>>(z, Wm + 4096, bm + 64, agg, NN, 1, nullptr,
                             nullptr, 0, nullptr, nullptr);
        gemm128<<<GB, 128>>>(agg, Wm + 8192, bm + 128, z, NN, 0, nullptr,
                             nullptr, 1, nullptr, nullptr);
        k_bn_finalize<<<1, 64>>>(ng + m * 64, nb + m * 64, 0);
        // c = 1: gather(bnrelu(z), slot 0) -> agg ; MLP
        k_gather<<<GTB, 256>>>(z, 1);
        gemm128<<<GB, 128>>>(agg, Wm, bm, z, NN, 1, nullptr, nullptr, 0,
                             nullptr, nullptr);
        gemm128<<<GB, 128>>>(z, Wm + 4096, bm + 64, agg, NN, 1, nullptr,
                             nullptr, 0, nullptr, nullptr);
        gemm128<<<GB, 128>>>(agg, Wm + 8192, bm + 128, z, NN, 0, nullptr,
                             nullptr, 1, nullptr, nullptr);
        k_bn_finalize<<<1, 64>>>(ng + m * 64, nb + m * 64, 1);
        // h = relu(bn(z)) + h   (res == h invariant)
        k_resid_fused<<<EW, 256>>>();
    }

    // attention: scores fused into Wk GEMM (K never materialized); V -> agg
    gemm128<<<GB, 128>>>(h, Wk, nullptr, nullptr, NN, 0, nullptr, nullptr, 0,
                         seed, sc);
    gemm128<<<GB, 128>>>(h, Wv, nullptr, agg, NN, 0, nullptr, nullptr, 0,
                         nullptr, nullptr);
    k_attn<<<NG, 128>>>();

    // embed = pooled @ Wo -> d_out[0 : NG*HD)
    gemm128<<<(NG + 127) / 128, 128>>>(pool, Wo, nullptr, out, NG, 0, nullptr,
                                       nullptr, 0, nullptr, nullptr);
    // logits -> d_out[NG*HD : ...)
    k_logits<<<NG, 128>>>(out, predW, predb, out + NG * HD);
}